// round 7
// baseline (speedup 1.0000x reference)
#include <cuda_runtime.h>
#include <cstdint>

// Problem constants (fixed shapes per reference)
#define B_   2
#define N_   16384
#define S_   4096        // npoint
#define C_   64
#define NS_  32          // nsample
#define NCID (B_*S_)     // 8192 centroids total

// Scratch (static __device__ arrays: allocation-free per harness rules)
__device__ float g_F1[(size_t)B_ * N_ * 64];   // feats@W1[3:] + b1, [b][n][64]  (8MB)
__device__ int   g_idx[NCID * NS_];            // ball query result               (1MB)

// ---------------------------------------------------------------------------
// Packed fp32x2 helpers (Blackwell FFMA2 — only reachable via PTX)
// ---------------------------------------------------------------------------
__device__ __forceinline__ unsigned long long ffma2(unsigned long long a,
                                                    unsigned long long b,
                                                    unsigned long long c) {
    unsigned long long d;
    asm("fma.rn.f32x2 %0, %1, %2, %3;" : "=l"(d) : "l"(a), "l"(b), "l"(c));
    return d;
}
__device__ __forceinline__ float p2sum(unsigned long long p) {
    unsigned lo, hi;
    asm("mov.b64 {%0, %1}, %2;" : "=r"(lo), "=r"(hi) : "l"(p));
    return __uint_as_float(lo) + __uint_as_float(hi);
}

// Swizzled smem layouts (rows of 64 floats = 16 chunks of 16B).
// Activations h[n][k]: rotate chunk by (n>>3) + 2*(n&7)  -> conflict-free for
// the stride-8-row read patterns in layers 2/3.
// Weights wT[c][k]:    rotate chunk by (c>>2)            -> conflict-free for
// the 4/8-distinct-c-row read patterns.
#define SWZH(n,kk) ( (n)*64 + (((((kk)>>2) + ((n)>>3) + 2*((n)&7)) & 15)<<2) + ((kk)&3) )
#define SWZW(c,kk) ( (c)*64 + (((((kk)>>2) + ((c)>>2)) & 15)<<2) + ((kk)&3) )

// ---------------------------------------------------------------------------
// Kernel 1: F1[b][n][j] = sum_c feats[b][c][n] * W1[3+c][j] + b1[j]
// grid (N/64, B), 256 threads
// ---------------------------------------------------------------------------
__global__ void k_f1(const float* __restrict__ feats,
                     const float* __restrict__ W1,
                     const float* __restrict__ b1) {
    __shared__ float sF[64 * 64];   // [c][n_local]
    __shared__ float sW[64 * 64];   // [c][j]
    __shared__ float sb[64];
    int b  = blockIdx.y;
    int n0 = blockIdx.x * 64;
    int tid = threadIdx.x;

    for (int i = tid; i < 4096; i += 256) sW[i] = W1[192 + i];  // rows 3..66
    if (tid < 64) sb[tid] = b1[tid];
    const float* fb = feats + (size_t)b * 64 * N_;
    for (int i = tid; i < 4096; i += 256) {
        int c = i >> 6, nn = i & 63;
        sF[c * 64 + nn] = fb[(size_t)c * N_ + n0 + nn];
    }
    __syncthreads();

    int n  = tid & 63;
    int j0 = (tid >> 6) * 16;
    float acc[16];
#pragma unroll
    for (int j = 0; j < 16; j++) acc[j] = sb[j0 + j];
#pragma unroll 8
    for (int c = 0; c < 64; c++) {
        float f = sF[c * 64 + n];
#pragma unroll
        for (int j = 0; j < 16; j++) acc[j] += f * sW[c * 64 + j0 + j];
    }
    float* dst = g_F1 + ((size_t)b * N_ + n0 + n) * 64 + j0;
#pragma unroll
    for (int j = 0; j < 16; j += 4) {
        float4 v = make_float4(acc[j], acc[j+1], acc[j+2], acc[j+3]);
        *(float4*)(dst + j) = v;
    }
}

// ---------------------------------------------------------------------------
// Kernel 2: ball query. One warp per centroid, 8 warps/block, smem point tiles.
// ---------------------------------------------------------------------------
__global__ void k_bq(const float* __restrict__ xyz) {
    const int TILE = 2048;
    __shared__ float spx[TILE], spy[TILE], spz[TILE], sn2[TILE];
    __shared__ int s_done;
    int tid  = threadIdx.x;
    int lane = tid & 31, w = tid >> 5;
    int cid  = blockIdx.x * 8 + w;
    int b = cid >> 12, s = cid & (S_ - 1);
    if (tid == 0) s_done = 0;

    const float* xb = xyz + (size_t)b * N_ * 3;
    float cx = xb[s*3], cy = xb[s*3+1], cz = xb[s*3+2];
    float cn2 = cx*cx + cy*cy + cz*cz;
    const float R2 = 0.4f * 0.4f;

    int  cnt = 0, firstn = 0;
    bool flagged = false;
    int* myidx = g_idx + cid * NS_;

    for (int t0 = 0; t0 < N_; t0 += TILE) {
        for (int i = tid; i < TILE; i += 256) {
            float x = xb[(t0+i)*3], y = xb[(t0+i)*3+1], z = xb[(t0+i)*3+2];
            spx[i] = x; spy[i] = y; spz[i] = z; sn2[i] = x*x + y*y + z*z;
        }
        __syncthreads();
        if (cnt < NS_) {
            for (int it = 0; it < TILE/32; it++) {
                int j = it*32 + lane;
                float d2 = cn2 + sn2[j] - 2.0f*(cx*spx[j] + cy*spy[j] + cz*spz[j]);
                bool hit = d2 < R2;
                unsigned mask = __ballot_sync(0xffffffffu, hit);
                if (mask) {
                    if (cnt == 0) firstn = t0 + it*32 + (__ffs(mask) - 1);
                    int pos = cnt + __popc(mask & ((1u << lane) - 1u));
                    if (hit && pos < NS_) myidx[pos] = t0 + j;
                    cnt += __popc(mask);
                    if (cnt >= NS_) break;
                }
            }
            if (cnt >= NS_ && !flagged) {
                flagged = true;
                if (lane == 0) atomicAdd(&s_done, 1);
            }
        }
        __syncthreads();
        if (s_done == 8) break;
    }
    if (cnt < NS_) {
        int fv = (cnt > 0) ? firstn : 0;
        if (lane < NS_ - cnt) myidx[cnt + lane] = fv;
    }
}

// ---------------------------------------------------------------------------
// Kernel 3: fused MLP + max-pool, FFMA2 (f32x2) with k-pair packing.
// h stored [n][k] swizzled; W2/W3 stored transposed [c][k] swizzled.
// Accumulators are f32x2 pairs (even-k lane, odd-k lane); one FADD at the end.
// ---------------------------------------------------------------------------
__global__ __launch_bounds__(128, 3)
void k_mlp(const float* __restrict__ xyz,
           const float* __restrict__ W1, const float* __restrict__ W2,
           const float* __restrict__ b2, const float* __restrict__ W3,
           const float* __restrict__ b3, float* __restrict__ outf) {
    extern __shared__ float sm[];
    float* sW2t = sm;            // 64c x 64k   (4096)
    float* sW3t = sm + 4096;     // 128c x 64k  (8192)
    float* sW1x = sW3t + 8192;   // 3*64
    float* sb2  = sW1x + 192;    // 64
    float* sb3  = sb2 + 64;      // 128
    float* h1T  = sb3 + 128;     // 32n x 64k   (2048)
    float* h2T  = h1T + 2048;    // 32n x 64k   (2048)
    int tid = threadIdx.x;

    // Transposed + swizzled weight staging
    for (int i = tid; i < 4096; i += 128) {
        int k = i >> 6, c = i & 63;
        sW2t[SWZW(c, k)] = W2[i];
    }
    for (int i = tid; i < 8192; i += 128) {
        int k = i >> 7, c = i & 127;
        sW3t[SWZW(c, k)] = W3[i];
    }
    if (tid < 64) { sW1x[tid] = W1[tid]; sW1x[64+tid] = W1[64+tid]; sW1x[128+tid] = W1[128+tid]; }
    if (tid < 64) sb2[tid] = b2[tid];
    sb3[tid] = b3[tid];
    __syncthreads();

    // Layer-1 mapping: n = tid&31, 16 j's per thread
    int n1  = tid & 31;
    int j0  = (tid >> 5) * 16;
    // Layer-2 mapping: 4n x 4c tiles
    int ng2 = tid & 7;   int n2 = ng2 * 4;
    int cg2 = tid >> 3;  int c2 = cg2 * 4;
    // Layer-3 mapping: 8n x 4c tiles
    int ng3 = tid & 3;   int n3 = ng3 * 8;
    int cg3 = tid >> 2;  int c3 = cg3 * 4;

    for (int ci = 0; ci < 8; ci++) {
        int cid = blockIdx.x * 8 + ci;
        int b = cid >> 12, s = cid & (S_ - 1);

        // ---- layer 1: h1[n][j] = relu(F1[idx[n]][j] + dxyz . W1xyz[:,j]) ----
        {
            int pidx = g_idx[cid * NS_ + n1];
            const float* xb = xyz + (size_t)b * N_ * 3;
            float dx = xb[pidx*3+0] - xb[s*3+0];
            float dy = xb[pidx*3+1] - xb[s*3+1];
            float dz = xb[pidx*3+2] - xb[s*3+2];
            const float* f1p = g_F1 + ((size_t)b * N_ + pidx) * 64 + j0;
#pragma unroll
            for (int q = 0; q < 4; q++) {
                float4 f = *(const float4*)(f1p + q*4);
                int j = j0 + q*4;
                float4 v;
                v.x = fmaxf(f.x + dx*sW1x[j+0] + dy*sW1x[64+j+0] + dz*sW1x[128+j+0], 0.f);
                v.y = fmaxf(f.y + dx*sW1x[j+1] + dy*sW1x[64+j+1] + dz*sW1x[128+j+1], 0.f);
                v.z = fmaxf(f.z + dx*sW1x[j+2] + dy*sW1x[64+j+2] + dz*sW1x[128+j+2], 0.f);
                v.w = fmaxf(f.w + dx*sW1x[j+3] + dy*sW1x[64+j+3] + dz*sW1x[128+j+3], 0.f);
                *(float4*)(h1T + SWZH(n1, j)) = v;
            }
        }
        __syncthreads();

        // ---- layer 2: h2[n][c] = relu(b2 + sum_k h1[n][k] W2[k][c]) ----
        {
            unsigned long long acc[4][4];
#pragma unroll
            for (int j = 0; j < 4; j++)
#pragma unroll
                for (int m = 0; m < 4; m++) acc[j][m] = 0ull;
#pragma unroll 2
            for (int kk = 0; kk < 64; kk += 4) {
                ulonglong2 A[4], Wv[4];
#pragma unroll
                for (int j = 0; j < 4; j++)
                    A[j] = *(const ulonglong2*)(h1T + SWZH(n2 + j, kk));
#pragma unroll
                for (int m = 0; m < 4; m++)
                    Wv[m] = *(const ulonglong2*)(sW2t + SWZW(c2 + m, kk));
#pragma unroll
                for (int j = 0; j < 4; j++)
#pragma unroll
                    for (int m = 0; m < 4; m++) {
                        acc[j][m] = ffma2(A[j].x, Wv[m].x, acc[j][m]);
                        acc[j][m] = ffma2(A[j].y, Wv[m].y, acc[j][m]);
                    }
            }
#pragma unroll
            for (int j = 0; j < 4; j++) {
                float4 v;
                v.x = fmaxf(p2sum(acc[j][0]) + sb2[c2+0], 0.f);
                v.y = fmaxf(p2sum(acc[j][1]) + sb2[c2+1], 0.f);
                v.z = fmaxf(p2sum(acc[j][2]) + sb2[c2+2], 0.f);
                v.w = fmaxf(p2sum(acc[j][3]) + sb2[c2+3], 0.f);
                *(float4*)(h2T + SWZH(n2 + j, c2)) = v;
            }
        }
        __syncthreads();

        // ---- layer 3 + relu + max over the 32 neighbors ----
        {
            unsigned long long acc[8][4];
#pragma unroll
            for (int j = 0; j < 8; j++)
#pragma unroll
                for (int m = 0; m < 4; m++) acc[j][m] = 0ull;
#pragma unroll 2
            for (int kk = 0; kk < 64; kk += 4) {
                ulonglong2 A[8], Wv[4];
#pragma unroll
                for (int j = 0; j < 8; j++)
                    A[j] = *(const ulonglong2*)(h2T + SWZH(n3 + j, kk));
#pragma unroll
                for (int m = 0; m < 4; m++)
                    Wv[m] = *(const ulonglong2*)(sW3t + SWZW(c3 + m, kk));
#pragma unroll
                for (int j = 0; j < 8; j++)
#pragma unroll
                    for (int m = 0; m < 4; m++) {
                        acc[j][m] = ffma2(A[j].x, Wv[m].x, acc[j][m]);
                        acc[j][m] = ffma2(A[j].y, Wv[m].y, acc[j][m]);
                    }
            }
            float mx[4];
#pragma unroll
            for (int m = 0; m < 4; m++) {
                float bm = sb3[c3 + m];
                float v = p2sum(acc[0][m]) + bm;
#pragma unroll
                for (int j = 1; j < 8; j++)
                    v = fmaxf(v, p2sum(acc[j][m]) + bm);
                mx[m] = fmaxf(v, 0.f);
            }
            // reduce across the 4 n-groups (lane bits 0-1)
#pragma unroll
            for (int off = 1; off < 4; off <<= 1)
#pragma unroll
                for (int m = 0; m < 4; m++)
                    mx[m] = fmaxf(mx[m], __shfl_xor_sync(0xffffffffu, mx[m], off));
            if (ng3 == 0) {
                float* o = outf + ((size_t)b * 128 + c3) * S_ + s;
#pragma unroll
                for (int m = 0; m < 4; m++) o[(size_t)m * S_] = mx[m];
            }
        }
        __syncthreads();
    }
}

// ---------------------------------------------------------------------------
// Kernel 4: new_xyz copy + samp_idx (as float values)
// ---------------------------------------------------------------------------
__global__ void k_out(const float* __restrict__ xyz, float* __restrict__ out) {
    int i = blockIdx.x * blockDim.x + threadIdx.x;
    if (i < B_ * S_ * 3) {
        int b = i / (S_ * 3), r = i % (S_ * 3);
        out[i] = xyz[(size_t)b * N_ * 3 + r];
    } else {
        int j = i - B_ * S_ * 3;
        if (j < B_ * S_)
            out[B_*S_*3 + (size_t)B_*128*S_ + j] = (float)(j & (S_ - 1));
    }
}

// ---------------------------------------------------------------------------
extern "C" void kernel_launch(void* const* d_in, const int* in_sizes, int n_in,
                              void* d_out, int out_size) {
    const float* xyz   = (const float*)d_in[0];
    const float* feats = (const float*)d_in[1];
    const float* W1    = (const float*)d_in[2];
    const float* b1    = (const float*)d_in[3];
    const float* W2    = (const float*)d_in[4];
    const float* b2    = (const float*)d_in[5];
    const float* W3    = (const float*)d_in[6];
    const float* b3    = (const float*)d_in[7];
    float* out = (float*)d_out;

    const int NXYZ = B_ * S_ * 3;               // 24576
    const int NFEA = B_ * 128 * S_;             // 1048576
    float* outf = out + NXYZ;                   // features region (full tuple layout)
    bool full_layout = (out_size >= NXYZ + NFEA + B_ * S_);
    if (!full_layout && out_size == NFEA) outf = out;  // features-only fallback

    const size_t smem_mlp = 16768 * sizeof(float);  // 67072 B
    cudaFuncSetAttribute(k_mlp, cudaFuncAttributeMaxDynamicSharedMemorySize,
                         (int)smem_mlp);

    k_f1<<<dim3(N_/64, B_), 256>>>(feats, W1, b1);
    k_bq<<<NCID/8, 256>>>(xyz);
    k_mlp<<<NCID/8, 128, smem_mlp>>>(xyz, W1, W2, b2, W3, b3, outf);
    if (full_layout) {
        int tot = NXYZ + B_ * S_;
        k_out<<<(tot + 255)/256, 256>>>(xyz, out);
    }
}